// round 3
// baseline (speedup 1.0000x reference)
#include <cuda_runtime.h>
#include <cuda_bf16.h>
#include <math.h>

// ---------------- problem constants ----------------
#define B_    512
#define A_    8
#define NN    42
#define NIN   32
#define H     128
#define BFN   3
#define NH    4
#define LL    2
#define FF    256
#define OUTD  128
#define EE    41
#define HD    32
#define FB    (B_*A_)        // 4096
#define TT    (FB*NN)        // 172032

// ---------------- scratch (no allocs allowed) ----------------
__device__ float g_x[(size_t)TT*H];        // activations
__device__ float g_pos[(size_t)TT*H];      // pos, reused as attention output
__device__ float g_qkv[(size_t)TT*3*H];    // qkv, reused as FF hidden
__device__ float g_fin[(size_t)FB*OUTD];   // final pre-LN accumulator

// ---------------- positional encoding ----------------
// pos[child] = pos[parent] + onehot(depth(parent)*BFN + clamp(slot+1,0,BFN-1))
__global__ __launch_bounds__(128) void pos_kernel(const int* __restrict__ adj,
                                                  const int* __restrict__ order,
                                                  float* __restrict__ pos)
{
    int fb = blockIdx.x;
    int h  = threadIdx.x;    // 0..127
    __shared__ int par[EE], chi[EE], slt[EE];
    __shared__ int dep[NN];
    __shared__ int maxo;
    __shared__ float ps[NN][H];   // 21.5 KB

    if (h < NN) dep[h] = order[fb*NN + h];
    if (h < EE) {
        const int* e = &adj[((size_t)fb*EE + h)*3];
        par[h] = e[0]; chi[h] = e[1]; slt[h] = e[2];
    }
    __syncthreads();
    if (h == 0) {
        int m = dep[0];
        for (int i = 1; i < NN; i++) m = max(m, dep[i]);
        maxo = m;
    }
    __syncthreads();
    if (h < NN) dep[h] = maxo - dep[h];
    for (int n = 0; n < NN; n++) ps[n][h] = 0.f;
    __syncthreads();

    for (int d = 0; d < NN; d++) {
        for (int e = 0; e < EE; e++) {
            int p = par[e], c = chi[e];
            if (p >= 0 && c >= 0) {
                int pl = p - fb*NN, cl = c - fb*NN;
                if (pl >= 0 && pl < NN && cl >= 0 && cl < NN && dep[pl] == d) {
                    int s = slt[e] + 1; s = min(max(s, 0), BFN-1);
                    int idx = d*BFN + s;
                    float add = (idx < H && h == idx) ? 1.f : 0.f;
                    ps[cl][h] = ps[pl][h] + add;
                }
            }
        }
        __syncthreads();
    }
    for (int n = 0; n < NN; n++)
        pos[((size_t)(fb*NN + n))*H + h] = ps[n][h];
}

// ---------------- generic SGEMM  C = A[M,K] @ W[N,K]^T  ----------------
#define BM 64
#define BN 128
#define BK 16

#define EPI_BIAS   0
#define EPI_RELU   1
#define EPI_ADD    2
#define EPI_RESLN  3
#define EPI_ATOMIC 4

template<int EPI>
__global__ __launch_bounds__(256)
void gemm_k(const float* __restrict__ Ag, const float* __restrict__ Wg,
            const float* __restrict__ bias, const float* __restrict__ resid,
            const float* __restrict__ gam,  const float* __restrict__ bet,
            float* __restrict__ Cg, int M, int N, int K, int k0, int k1)
{
    __shared__ __align__(16) float As[BK][BM];
    __shared__ __align__(16) float Ws[BK][BN];

    int m0 = blockIdx.x * BM;
    int n0 = blockIdx.y * BN;
    int span = k1 - k0;
    int per  = span / gridDim.z;
    int ks   = k0 + blockIdx.z * per;
    int ke   = ks + per;

    int tid = threadIdx.x;
    int tx = tid & 15;     // col groups
    int ty = tid >> 4;     // row groups

    int arow = tid >> 2, acol = (tid & 3) * 4;
    int wrow = tid >> 1, wcol = (tid & 1) * 8;

    float acc[4][8];
#pragma unroll
    for (int j = 0; j < 4; j++)
#pragma unroll
        for (int i = 0; i < 8; i++) acc[j][i] = 0.f;

    for (int kt = ks; kt < ke; kt += BK) {
        __syncthreads();
        float4 av = *(const float4*)&Ag[(size_t)(m0 + arow)*K + kt + acol];
        As[acol+0][arow] = av.x; As[acol+1][arow] = av.y;
        As[acol+2][arow] = av.z; As[acol+3][arow] = av.w;
        float4 w0 = *(const float4*)&Wg[(size_t)(n0 + wrow)*K + kt + wcol];
        float4 w1 = *(const float4*)&Wg[(size_t)(n0 + wrow)*K + kt + wcol + 4];
        Ws[wcol+0][wrow] = w0.x; Ws[wcol+1][wrow] = w0.y;
        Ws[wcol+2][wrow] = w0.z; Ws[wcol+3][wrow] = w0.w;
        Ws[wcol+4][wrow] = w1.x; Ws[wcol+5][wrow] = w1.y;
        Ws[wcol+6][wrow] = w1.z; Ws[wcol+7][wrow] = w1.w;
        __syncthreads();
#pragma unroll
        for (int k = 0; k < BK; k++) {
            float4 a4  = *(const float4*)&As[k][ty*4];
            float4 blo = *(const float4*)&Ws[k][tx*4];
            float4 bhi = *(const float4*)&Ws[k][64 + tx*4];
            float aa[4] = {a4.x, a4.y, a4.z, a4.w};
#pragma unroll
            for (int j = 0; j < 4; j++) {
                acc[j][0] += aa[j]*blo.x; acc[j][1] += aa[j]*blo.y;
                acc[j][2] += aa[j]*blo.z; acc[j][3] += aa[j]*blo.w;
                acc[j][4] += aa[j]*bhi.x; acc[j][5] += aa[j]*bhi.y;
                acc[j][6] += aa[j]*bhi.z; acc[j][7] += aa[j]*bhi.w;
            }
        }
    }

    if constexpr (EPI == EPI_BIAS || EPI == EPI_RELU || EPI == EPI_ADD) {
#pragma unroll
        for (int j = 0; j < 4; j++) {
            size_t r = (size_t)(m0 + ty*4 + j);
#pragma unroll
            for (int i = 0; i < 4; i++) {
                int cl = tx*4 + i, ch = 64 + tx*4 + i;
                float vl = acc[j][i]   + bias[n0 + cl];
                float vh = acc[j][4+i] + bias[n0 + ch];
                if constexpr (EPI == EPI_RELU) { vl = fmaxf(vl, 0.f); vh = fmaxf(vh, 0.f); }
                if constexpr (EPI == EPI_ADD) {
                    vl += resid[r*(size_t)N + n0 + cl];
                    vh += resid[r*(size_t)N + n0 + ch];
                }
                Cg[r*(size_t)N + n0 + cl] = vl;
                Cg[r*(size_t)N + n0 + ch] = vh;
            }
        }
    }
    if constexpr (EPI == EPI_ATOMIC) {
#pragma unroll
        for (int j = 0; j < 4; j++) {
            size_t r = (size_t)(m0 + ty*4 + j);
#pragma unroll
            for (int i = 0; i < 4; i++) {
                atomicAdd(&Cg[r*(size_t)N + n0 + tx*4 + i],      acc[j][i]);
                atomicAdd(&Cg[r*(size_t)N + n0 + 64 + tx*4 + i], acc[j][4+i]);
            }
        }
    }
    if constexpr (EPI == EPI_RESLN) {   // N must be 128, n0 == 0
        __shared__ float tile[BM][BN + 1];
        __shared__ float psum[4][BM];
        __shared__ float mu_s[BM], rs_s[BM];
#pragma unroll
        for (int j = 0; j < 4; j++) {
            int rr = ty*4 + j;
            size_t r = (size_t)(m0 + rr);
#pragma unroll
            for (int i = 0; i < 4; i++) {
                int cl = tx*4 + i, ch = 64 + tx*4 + i;
                tile[rr][cl] = acc[j][i]   + bias[cl] + resid[r*128 + cl];
                tile[rr][ch] = acc[j][4+i] + bias[ch] + resid[r*128 + ch];
            }
        }
        __syncthreads();
        int row = tid & 63, part = tid >> 6;
        float s = 0.f;
#pragma unroll
        for (int k2 = 0; k2 < 32; k2++) s += tile[row][part*32 + k2];
        psum[part][row] = s;
        __syncthreads();
        if (tid < 64)
            mu_s[tid] = (psum[0][tid] + psum[1][tid] + psum[2][tid] + psum[3][tid]) * (1.f/128.f);
        __syncthreads();
        float mu = mu_s[row];
        float v = 0.f;
#pragma unroll
        for (int k2 = 0; k2 < 32; k2++) { float d = tile[row][part*32 + k2] - mu; v += d*d; }
        __syncthreads();               // ensure mu reads done before psum reuse
        psum[part][row] = v;
        __syncthreads();
        if (tid < 64)
            rs_s[tid] = rsqrtf((psum[0][tid] + psum[1][tid] + psum[2][tid] + psum[3][tid]) * (1.f/128.f) + 1e-5f);
        __syncthreads();
        float rs = rs_s[row];
        size_t r = (size_t)(m0 + row);
#pragma unroll
        for (int k2 = 0; k2 < 32; k2++) {
            int c = part*32 + k2;
            Cg[r*128 + c] = (tile[row][c] - mu) * rs * gam[c] + bet[c];
        }
    }
}

// ---------------- attention: one block per forest, warp per head ----------------
__global__ __launch_bounds__(128) void attn_k(const float* __restrict__ qkv,
                                              float* __restrict__ o)
{
    int fb = blockIdx.x;
    __shared__ float ks_[NN][H + 1];
    __shared__ float vs_[NN][H + 1];
    __shared__ float pr[NH][64];

    int tid = threadIdx.x;
    for (int idx = tid; idx < NN*H; idx += 128) {
        int n = idx >> 7, c = idx & 127;
        const float* row = &qkv[((size_t)(fb*NN + n))*(3*H)];
        ks_[n][c] = row[H + c];
        vs_[n][c] = row[2*H + c];
    }
    __syncthreads();

    int h = tid >> 5, lane = tid & 31;
    int hc = h * HD;
    const float scale = 0.17677669529663687f;   // 1/sqrt(32)

    for (int i = 0; i < NN; i++) {
        const float* qrow = &qkv[((size_t)(fb*NN + i))*(3*H) + hc];
        float q[HD];
#pragma unroll
        for (int d = 0; d < HD; d++) q[d] = qrow[d];

        float s0, s1 = -1e30f;
        {
            float acc = 0.f;
#pragma unroll
            for (int d = 0; d < HD; d++) acc += q[d] * ks_[lane][hc + d];
            s0 = acc * scale;
        }
        if (lane + 32 < NN) {
            float acc = 0.f;
#pragma unroll
            for (int d = 0; d < HD; d++) acc += q[d] * ks_[lane + 32][hc + d];
            s1 = acc * scale;
        }
        float m = fmaxf(s0, s1);
#pragma unroll
        for (int off = 16; off; off >>= 1) m = fmaxf(m, __shfl_xor_sync(0xffffffffu, m, off));
        float p0 = __expf(s0 - m);
        float p1 = (lane + 32 < NN) ? __expf(s1 - m) : 0.f;
        float sum = p0 + p1;
#pragma unroll
        for (int off = 16; off; off >>= 1) sum += __shfl_xor_sync(0xffffffffu, sum, off);
        float inv = 1.f / sum;
        pr[h][lane]      = p0 * inv;
        pr[h][lane + 32] = p1 * inv;
        __syncwarp();
        float acc = 0.f;
#pragma unroll
        for (int j = 0; j < NN; j++) acc += pr[h][j] * vs_[j][hc + lane];
        o[((size_t)(fb*NN + i))*H + hc + lane] = acc;
        __syncwarp();
    }
}

// ---------------- final LN over OUT=128 ----------------
__global__ __launch_bounds__(128) void lnf_k(const float* __restrict__ fin,
                                             const float* __restrict__ bo,
                                             const float* __restrict__ g,
                                             const float* __restrict__ b,
                                             float* __restrict__ out)
{
    int r = blockIdx.x, c = threadIdx.x;
    float v = fin[(size_t)r*OUTD + c] + bo[c];
    __shared__ float red[4];
    float s = v;
#pragma unroll
    for (int off = 16; off; off >>= 1) s += __shfl_xor_sync(0xffffffffu, s, off);
    if ((c & 31) == 0) red[c >> 5] = s;
    __syncthreads();
    float mu = (red[0] + red[1] + red[2] + red[3]) * (1.f/128.f);
    __syncthreads();
    float d = v - mu;
    float q = d * d;
#pragma unroll
    for (int off = 16; off; off >>= 1) q += __shfl_xor_sync(0xffffffffu, q, off);
    if ((c & 31) == 0) red[c >> 5] = q;
    __syncthreads();
    float var = (red[0] + red[1] + red[2] + red[3]) * (1.f/128.f);
    float rs = rsqrtf(var + 1e-5f);
    out[(size_t)r*OUTD + c] = d * rs * g[c] + b[c];
}

// ---------------- launch ----------------
extern "C" void kernel_launch(void* const* d_in, const int* in_sizes, int n_in,
                              void* d_out, int out_size)
{
    const float* forest = (const float*)d_in[0];
    const int*   adj    = (const int*)  d_in[1];
    const int*   order  = (const int*)  d_in[2];
    const float* W_in   = (const float*)d_in[3];
    const float* b_in   = (const float*)d_in[4];
    const float* qkv_w  = (const float*)d_in[5];
    const float* qkv_b  = (const float*)d_in[6];
    const float* aow    = (const float*)d_in[7];
    const float* aob    = (const float*)d_in[8];
    const float* f1w    = (const float*)d_in[9];
    const float* f1b    = (const float*)d_in[10];
    const float* f2w    = (const float*)d_in[11];
    const float* f2b    = (const float*)d_in[12];
    const float* ln1g   = (const float*)d_in[13];
    const float* ln1b   = (const float*)d_in[14];
    const float* ln2g   = (const float*)d_in[15];
    const float* ln2b   = (const float*)d_in[16];
    const float* Wout   = (const float*)d_in[17];
    const float* bout   = (const float*)d_in[18];
    const float* lnfg   = (const float*)d_in[19];
    const float* lnfb   = (const float*)d_in[20];

    float *px, *ppos, *pqkv, *pfin;
    cudaGetSymbolAddress((void**)&px,   g_x);
    cudaGetSymbolAddress((void**)&ppos, g_pos);
    cudaGetSymbolAddress((void**)&pqkv, g_qkv);
    cudaGetSymbolAddress((void**)&pfin, g_fin);

    // 1) positional encoding
    pos_kernel<<<FB, 128>>>(adj, order, ppos);

    // 2) embed: x = forest @ W_in^T + b_in + pos
    gemm_k<EPI_ADD><<<dim3(TT/BM, 1, 1), 256>>>(
        forest, W_in, b_in, ppos, nullptr, nullptr, px, TT, H, NIN, 0, NIN);

    for (int l = 0; l < LL; l++) {
        // qkv
        gemm_k<EPI_BIAS><<<dim3(TT/BM, 3, 1), 256>>>(
            px, qkv_w + (size_t)l*3*H*H, qkv_b + (size_t)l*3*H,
            nullptr, nullptr, nullptr, pqkv, TT, 3*H, H, 0, H);
        // attention -> ppos (reuse)
        attn_k<<<FB, 128>>>(pqkv, ppos);
        // o-proj + residual + LN1 (in-place on x)
        gemm_k<EPI_RESLN><<<dim3(TT/BM, 1, 1), 256>>>(
            ppos, aow + (size_t)l*H*H, aob + (size_t)l*H,
            px, ln1g + (size_t)l*H, ln1b + (size_t)l*H, px, TT, H, H, 0, H);
        // ff1 + relu -> pqkv (reuse)
        gemm_k<EPI_RELU><<<dim3(TT/BM, 2, 1), 256>>>(
            px, f1w + (size_t)l*FF*H, f1b + (size_t)l*FF,
            nullptr, nullptr, nullptr, pqkv, TT, FF, H, 0, H);
        // ff2 + residual + LN2 (in-place on x)
        gemm_k<EPI_RESLN><<<dim3(TT/BM, 1, 1), 256>>>(
            pqkv, f2w + (size_t)l*H*FF, f2b + (size_t)l*H,
            px, ln2g + (size_t)l*H, ln2b + (size_t)l*H, px, TT, H, FF, 0, FF);
    }

    // 3) final: out = LN( x.reshape(FB, NN*H) @ Wout^T + b_out )
    cudaMemsetAsync(pfin, 0, (size_t)FB*OUTD*sizeof(float));
    gemm_k<EPI_ATOMIC><<<dim3(FB/BM, 1, 8), 256>>>(
        px, Wout, nullptr, nullptr, nullptr, nullptr, pfin, FB, OUTD, NN*H, 0, NN*H);
    lnf_k<<<FB, 128>>>(pfin, bout, lnfg, lnfb, (float*)d_out);
}

// round 4
// speedup vs baseline: 1.5716x; 1.5716x over previous
#include <cuda_runtime.h>
#include <cuda_bf16.h>
#include <math.h>

// ---------------- problem constants ----------------
#define B_    512
#define A_    8
#define NN    42
#define NIN   32
#define H     128
#define BFN   3
#define NH    4
#define LL    2
#define FF    256
#define OUTD  128
#define EE    41
#define HD    32
#define FB    (B_*A_)        // 4096
#define TT    (FB*NN)        // 172032

// ---------------- scratch (no allocs allowed) ----------------
__device__ float g_x[(size_t)TT*H];        // activations
__device__ float g_pos[(size_t)TT*H];      // pos / attn-out / ff2-out
__device__ float g_qkv[(size_t)TT*3*H];    // qkv / ff-hidden / oproj-out
__device__ float g_fin[(size_t)FB*OUTD];   // final pre-LN accumulator

// ---------------- positional encoding ----------------
__global__ __launch_bounds__(128) void pos_kernel(const int* __restrict__ adj,
                                                  const int* __restrict__ order,
                                                  float* __restrict__ pos)
{
    int fb = blockIdx.x;
    int h  = threadIdx.x;    // 0..127
    __shared__ int par[EE], chi[EE], slt[EE];
    __shared__ int dep[NN];
    __shared__ int maxo;
    __shared__ float ps[NN][H];

    if (h < NN) dep[h] = order[fb*NN + h];
    if (h < EE) {
        const int* e = &adj[((size_t)fb*EE + h)*3];
        par[h] = e[0]; chi[h] = e[1]; slt[h] = e[2];
    }
    __syncthreads();
    if (h == 0) {
        int m = dep[0];
        for (int i = 1; i < NN; i++) m = max(m, dep[i]);
        maxo = m;
    }
    __syncthreads();
    if (h < NN) dep[h] = maxo - dep[h];
    for (int n = 0; n < NN; n++) ps[n][h] = 0.f;
    __syncthreads();

    for (int d = 0; d < NN; d++) {
        for (int e = 0; e < EE; e++) {
            int p = par[e], c = chi[e];
            if (p >= 0 && c >= 0) {
                int pl = p - fb*NN, cl = c - fb*NN;
                if (pl >= 0 && pl < NN && cl >= 0 && cl < NN && dep[pl] == d) {
                    int s = slt[e] + 1; s = min(max(s, 0), BFN-1);
                    int idx = d*BFN + s;
                    float add = (idx < H && h == idx) ? 1.f : 0.f;
                    ps[cl][h] = ps[pl][h] + add;
                }
            }
        }
        __syncthreads();
    }
    for (int n = 0; n < NN; n++)
        pos[((size_t)(fb*NN + n))*H + h] = ps[n][h];
}

// ---------------- TF32 tensor-core GEMM  C = A[M,K] @ W[N,K]^T ----------------
__device__ __forceinline__ unsigned f2tf(float f)
{
    unsigned u;
    asm("cvt.rna.tf32.f32 %0, %1;" : "=r"(u) : "f"(f));
    return u;
}

#define BM  128
#define BN  128
#define BK  16
#define LDK 20       // padded k-stride (words): frag LDS provably conflict-free

#define EPI_BIAS   0
#define EPI_RELU   1
#define EPI_ADD    2
#define EPI_ATOMIC 3

template<int EPI>
__global__ __launch_bounds__(256)
void gemm_tc(const float* __restrict__ Ag, const float* __restrict__ Wg,
             const float* __restrict__ bias, const float* __restrict__ resid,
             float* __restrict__ Cg, int M, int N, int K)
{
    __shared__ unsigned As[BM][LDK];   // [m][k]
    __shared__ unsigned Bs[BN][LDK];   // [n][k]

    int m0 = blockIdx.x * BM;
    int n0 = blockIdx.y * BN;
    int per = K / gridDim.z;
    int ks  = blockIdx.z * per;
    int ke  = ks + per;

    int tid  = threadIdx.x;
    int lane = tid & 31;
    int warp = tid >> 5;
    int wm = warp >> 2;          // 0..1  (64-row slab)
    int wn = warp & 3;           // 0..3  (32-col slab)
    int gid = lane >> 2;         // 0..7
    int tg  = lane & 3;          // 0..3
    int lrow = tid >> 1;         // 0..127
    int lcol = (tid & 1) * 8;    // 0 or 8

    float acc[4][4][4];
#pragma unroll
    for (int i = 0; i < 4; i++)
#pragma unroll
        for (int j = 0; j < 4; j++)
#pragma unroll
            for (int k = 0; k < 4; k++) acc[i][j][k] = 0.f;

    const float* Ap = Ag + (size_t)(m0 + lrow) * K + lcol;
    const float* Wp = Wg + (size_t)(n0 + lrow) * K + lcol;

    for (int kt = ks; kt < ke; kt += BK) {
        float4 av0 = *(const float4*)(Ap + kt);
        float4 av1 = *(const float4*)(Ap + kt + 4);
        float4 wv0 = *(const float4*)(Wp + kt);
        float4 wv1 = *(const float4*)(Wp + kt + 4);
        __syncthreads();
        *(uint4*)&As[lrow][lcol]     = make_uint4(f2tf(av0.x), f2tf(av0.y), f2tf(av0.z), f2tf(av0.w));
        *(uint4*)&As[lrow][lcol + 4] = make_uint4(f2tf(av1.x), f2tf(av1.y), f2tf(av1.z), f2tf(av1.w));
        *(uint4*)&Bs[lrow][lcol]     = make_uint4(f2tf(wv0.x), f2tf(wv0.y), f2tf(wv0.z), f2tf(wv0.w));
        *(uint4*)&Bs[lrow][lcol + 4] = make_uint4(f2tf(wv1.x), f2tf(wv1.y), f2tf(wv1.z), f2tf(wv1.w));
        __syncthreads();

#pragma unroll
        for (int k2 = 0; k2 < 2; k2++) {
            int kk = k2 * 8;
            unsigned af[4][4], bf[4][2];
#pragma unroll
            for (int mt = 0; mt < 4; mt++) {
                int r = wm*64 + mt*16 + gid;
                af[mt][0] = As[r    ][kk + tg];
                af[mt][1] = As[r + 8][kk + tg];
                af[mt][2] = As[r    ][kk + tg + 4];
                af[mt][3] = As[r + 8][kk + tg + 4];
            }
#pragma unroll
            for (int nt = 0; nt < 4; nt++) {
                int c = wn*32 + nt*8 + gid;
                bf[nt][0] = Bs[c][kk + tg];
                bf[nt][1] = Bs[c][kk + tg + 4];
            }
#pragma unroll
            for (int mt = 0; mt < 4; mt++)
#pragma unroll
                for (int nt = 0; nt < 4; nt++) {
                    asm volatile(
                        "mma.sync.aligned.m16n8k8.row.col.f32.tf32.tf32.f32 "
                        "{%0,%1,%2,%3}, {%4,%5,%6,%7}, {%8,%9}, {%0,%1,%2,%3};\n"
                        : "+f"(acc[mt][nt][0]), "+f"(acc[mt][nt][1]),
                          "+f"(acc[mt][nt][2]), "+f"(acc[mt][nt][3])
                        : "r"(af[mt][0]), "r"(af[mt][1]), "r"(af[mt][2]), "r"(af[mt][3]),
                          "r"(bf[nt][0]), "r"(bf[nt][1]));
                }
        }
    }

#pragma unroll
    for (int mt = 0; mt < 4; mt++) {
#pragma unroll
        for (int nt = 0; nt < 4; nt++) {
            int r = m0 + wm*64 + mt*16 + gid;
            int c = n0 + wn*32 + nt*8 + 2*tg;
            if constexpr (EPI == EPI_ATOMIC) {
                atomicAdd(&Cg[(size_t)r*N + c],         acc[mt][nt][0]);
                atomicAdd(&Cg[(size_t)r*N + c + 1],     acc[mt][nt][1]);
                atomicAdd(&Cg[(size_t)(r+8)*N + c],     acc[mt][nt][2]);
                atomicAdd(&Cg[(size_t)(r+8)*N + c + 1], acc[mt][nt][3]);
            } else {
                float b0 = bias[c], b1 = bias[c + 1];
                float v0 = acc[mt][nt][0] + b0, v1 = acc[mt][nt][1] + b1;
                float v2 = acc[mt][nt][2] + b0, v3 = acc[mt][nt][3] + b1;
                if constexpr (EPI == EPI_RELU) {
                    v0 = fmaxf(v0, 0.f); v1 = fmaxf(v1, 0.f);
                    v2 = fmaxf(v2, 0.f); v3 = fmaxf(v3, 0.f);
                }
                if constexpr (EPI == EPI_ADD) {
                    float2 rl = *(const float2*)&resid[(size_t)r*N + c];
                    float2 rh = *(const float2*)&resid[(size_t)(r+8)*N + c];
                    v0 += rl.x; v1 += rl.y; v2 += rh.x; v3 += rh.y;
                }
                *(float2*)&Cg[(size_t)r*N + c]     = make_float2(v0, v1);
                *(float2*)&Cg[(size_t)(r+8)*N + c] = make_float2(v2, v3);
            }
        }
    }
}

// ---------------- row LayerNorm over H=128 (2 rows / 256-thread block) --------
__global__ __launch_bounds__(256) void ln_k(const float* __restrict__ src,
                                            const float* __restrict__ g,
                                            const float* __restrict__ b,
                                            float* __restrict__ dst)
{
    int half = threadIdx.x >> 7;          // 0/1
    int c    = threadIdx.x & 127;
    size_t r = (size_t)blockIdx.x * 2 + half;
    float v = src[r*128 + c];
    __shared__ float red[2][4];
    int w = c >> 5, lane = c & 31;
    float s = v;
#pragma unroll
    for (int off = 16; off; off >>= 1) s += __shfl_xor_sync(0xffffffffu, s, off);
    if (lane == 0) red[half][w] = s;
    __syncthreads();
    float mu = (red[half][0] + red[half][1] + red[half][2] + red[half][3]) * (1.f/128.f);
    __syncthreads();
    float d = v - mu;
    float q = d * d;
#pragma unroll
    for (int off = 16; off; off >>= 1) q += __shfl_xor_sync(0xffffffffu, q, off);
    if (lane == 0) red[half][w] = q;
    __syncthreads();
    float var = (red[half][0] + red[half][1] + red[half][2] + red[half][3]) * (1.f/128.f);
    dst[r*128 + c] = d * rsqrtf(var + 1e-5f) * g[c] + b[c];
}

// ---------------- attention: block per forest, warp per head, V in regs ------
__global__ __launch_bounds__(128) void attn_k(const float* __restrict__ qkv,
                                              float* __restrict__ o)
{
    int fb = blockIdx.x;
    __shared__ float ks_[NN][H + 1];
    __shared__ float pr[NH][64];

    int tid = threadIdx.x;
    for (int idx = tid; idx < NN*H; idx += 128) {
        int n = idx >> 7, c = idx & 127;
        ks_[n][c] = qkv[((size_t)(fb*NN + n))*(3*H) + H + c];
    }

    int h = tid >> 5, lane = tid & 31;
    int hc = h * HD;

    float v[NN];
#pragma unroll
    for (int j = 0; j < NN; j++)
        v[j] = qkv[((size_t)(fb*NN + j))*(3*H) + 2*H + hc + lane];
    __syncthreads();

    const float scale = 0.17677669529663687f;   // 1/sqrt(32)

    for (int i = 0; i < NN; i++) {
        const float* qrow = &qkv[((size_t)(fb*NN + i))*(3*H) + hc];
        float q[HD];
#pragma unroll
        for (int d = 0; d < HD; d++) q[d] = qrow[d];

        float s0, s1 = -1e30f;
        {
            float acc = 0.f;
#pragma unroll
            for (int d = 0; d < HD; d++) acc += q[d] * ks_[lane][hc + d];
            s0 = acc * scale;
        }
        if (lane + 32 < NN) {
            float acc = 0.f;
#pragma unroll
            for (int d = 0; d < HD; d++) acc += q[d] * ks_[lane + 32][hc + d];
            s1 = acc * scale;
        }
        float m = fmaxf(s0, s1);
#pragma unroll
        for (int off = 16; off; off >>= 1) m = fmaxf(m, __shfl_xor_sync(0xffffffffu, m, off));
        float p0 = __expf(s0 - m);
        float p1 = (lane + 32 < NN) ? __expf(s1 - m) : 0.f;
        float sum = p0 + p1;
#pragma unroll
        for (int off = 16; off; off >>= 1) sum += __shfl_xor_sync(0xffffffffu, sum, off);
        float inv = 1.f / sum;
        pr[h][lane]      = p0 * inv;
        pr[h][lane + 32] = p1 * inv;
        __syncwarp();
        float acc = 0.f;
#pragma unroll
        for (int j = 0; j < NN; j++) acc += pr[h][j] * v[j];
        o[((size_t)(fb*NN + i))*H + hc + lane] = acc;
        __syncwarp();
    }
}

// ---------------- final LN over OUT=128 ----------------
__global__ __launch_bounds__(128) void lnf_k(const float* __restrict__ fin,
                                             const float* __restrict__ bo,
                                             const float* __restrict__ g,
                                             const float* __restrict__ b,
                                             float* __restrict__ out)
{
    int r = blockIdx.x, c = threadIdx.x;
    float v = fin[(size_t)r*OUTD + c] + bo[c];
    __shared__ float red[4];
    float s = v;
#pragma unroll
    for (int off = 16; off; off >>= 1) s += __shfl_xor_sync(0xffffffffu, s, off);
    if ((c & 31) == 0) red[c >> 5] = s;
    __syncthreads();
    float mu = (red[0] + red[1] + red[2] + red[3]) * (1.f/128.f);
    __syncthreads();
    float d = v - mu;
    float q = d * d;
#pragma unroll
    for (int off = 16; off; off >>= 1) q += __shfl_xor_sync(0xffffffffu, q, off);
    if ((c & 31) == 0) red[c >> 5] = q;
    __syncthreads();
    float var = (red[0] + red[1] + red[2] + red[3]) * (1.f/128.f);
    float rs = rsqrtf(var + 1e-5f);
    out[(size_t)r*OUTD + c] = d * rs * g[c] + b[c];
}

// ---------------- launch ----------------
extern "C" void kernel_launch(void* const* d_in, const int* in_sizes, int n_in,
                              void* d_out, int out_size)
{
    const float* forest = (const float*)d_in[0];
    const int*   adj    = (const int*)  d_in[1];
    const int*   order  = (const int*)  d_in[2];
    const float* W_in   = (const float*)d_in[3];
    const float* b_in   = (const float*)d_in[4];
    const float* qkv_w  = (const float*)d_in[5];
    const float* qkv_b  = (const float*)d_in[6];
    const float* aow    = (const float*)d_in[7];
    const float* aob    = (const float*)d_in[8];
    const float* f1w    = (const float*)d_in[9];
    const float* f1b    = (const float*)d_in[10];
    const float* f2w    = (const float*)d_in[11];
    const float* f2b    = (const float*)d_in[12];
    const float* ln1g   = (const float*)d_in[13];
    const float* ln1b   = (const float*)d_in[14];
    const float* ln2g   = (const float*)d_in[15];
    const float* ln2b   = (const float*)d_in[16];
    const float* Wout   = (const float*)d_in[17];
    const float* bout   = (const float*)d_in[18];
    const float* lnfg   = (const float*)d_in[19];
    const float* lnfb   = (const float*)d_in[20];

    float *px, *ppos, *pqkv, *pfin;
    cudaGetSymbolAddress((void**)&px,   g_x);
    cudaGetSymbolAddress((void**)&ppos, g_pos);
    cudaGetSymbolAddress((void**)&pqkv, g_qkv);
    cudaGetSymbolAddress((void**)&pfin, g_fin);

    // 1) positional encoding
    pos_kernel<<<FB, 128>>>(adj, order, ppos);

    // 2) embed: x = forest @ W_in^T + b_in + pos
    gemm_tc<EPI_ADD><<<dim3(TT/BM, 1, 1), 256>>>(
        forest, W_in, b_in, ppos, px, TT, H, NIN);

    for (int l = 0; l < LL; l++) {
        // qkv = x @ qkv_w^T + b    (N = 384)
        gemm_tc<EPI_BIAS><<<dim3(TT/BM, 3, 1), 256>>>(
            px, qkv_w + (size_t)l*3*H*H, qkv_b + (size_t)l*3*H,
            nullptr, pqkv, TT, 3*H, H);
        // attention -> ppos
        attn_k<<<FB, 128>>>(pqkv, ppos);
        // t = attn_out @ aow^T + aob + x  -> pqkv ; then LN -> x
        gemm_tc<EPI_ADD><<<dim3(TT/BM, 1, 1), 256>>>(
            ppos, aow + (size_t)l*H*H, aob + (size_t)l*H, px, pqkv, TT, H, H);
        ln_k<<<TT/2, 256>>>(pqkv, ln1g + (size_t)l*H, ln1b + (size_t)l*H, px);
        // ff hidden = relu(x @ f1w^T + f1b)  -> pqkv (N = 256)
        gemm_tc<EPI_RELU><<<dim3(TT/BM, 2, 1), 256>>>(
            px, f1w + (size_t)l*FF*H, f1b + (size_t)l*FF, nullptr, pqkv, TT, FF, H);
        // t = hidden @ f2w^T + f2b + x -> ppos ; then LN -> x
        gemm_tc<EPI_ADD><<<dim3(TT/BM, 1, 1), 256>>>(
            pqkv, f2w + (size_t)l*H*FF, f2b + (size_t)l*H, px, ppos, TT, H, FF);
        ln_k<<<TT/2, 256>>>(ppos, ln2g + (size_t)l*H, ln2b + (size_t)l*H, px);
    }

    // 3) final: out = LN( x.reshape(FB, NN*H) @ Wout^T + b_out )
    cudaMemsetAsync(pfin, 0, (size_t)FB*OUTD*sizeof(float));
    gemm_tc<EPI_ATOMIC><<<dim3(FB/BM, 1, 8), 256>>>(
        px, Wout, nullptr, nullptr, pfin, FB, OUTD, NN*H);
    lnf_k<<<FB, 128>>>(pfin, bout, lnfg, lnfb, (float*)d_out);
}

// round 6
// speedup vs baseline: 1.6379x; 1.0422x over previous
#include <cuda_runtime.h>
#include <cuda_bf16.h>
#include <math.h>

// ---------------- problem constants ----------------
#define B_    512
#define A_    8
#define NN    42
#define NIN   32
#define H     128
#define BFN   3
#define NH    4
#define LL    2
#define FF    256
#define OUTD  128
#define EE    41
#define HD    32
#define FB    (B_*A_)        // 4096
#define TT    (FB*NN)        // 172032

// ---------------- scratch (no allocs allowed) ----------------
__device__ float g_x[(size_t)TT*H];        // activations
__device__ float g_pos[(size_t)TT*H];      // pos / attn-out / ff2-out
__device__ float g_qkv[(size_t)TT*3*H];    // qkv / ff-hidden / oproj-out
__device__ float g_fin[(size_t)FB*OUTD];   // final pre-LN accumulator

// ---------------- positional encoding ----------------
__global__ __launch_bounds__(128) void pos_kernel(const int* __restrict__ adj,
                                                  const int* __restrict__ order,
                                                  float* __restrict__ pos)
{
    int fb = blockIdx.x;
    int h  = threadIdx.x;    // 0..127
    __shared__ int par[EE], chi[EE], slt[EE];
    __shared__ int dep[NN];
    __shared__ int maxo;
    __shared__ float ps[NN][H];

    if (h < NN) dep[h] = order[fb*NN + h];
    if (h < EE) {
        const int* e = &adj[((size_t)fb*EE + h)*3];
        par[h] = e[0]; chi[h] = e[1]; slt[h] = e[2];
    }
    __syncthreads();
    if (h == 0) {
        int m = dep[0];
        for (int i = 1; i < NN; i++) m = max(m, dep[i]);
        maxo = m;
    }
    __syncthreads();
    if (h < NN) dep[h] = maxo - dep[h];
    for (int n = 0; n < NN; n++) ps[n][h] = 0.f;
    __syncthreads();

    for (int d = 0; d < NN; d++) {
        for (int e = 0; e < EE; e++) {
            int p = par[e], c = chi[e];
            if (p >= 0 && c >= 0) {
                int pl = p - fb*NN, cl = c - fb*NN;
                if (pl >= 0 && pl < NN && cl >= 0 && cl < NN && dep[pl] == d) {
                    int s = slt[e] + 1; s = min(max(s, 0), BFN-1);
                    int idx = d*BFN + s;
                    float add = (idx < H && h == idx) ? 1.f : 0.f;
                    ps[cl][h] = ps[pl][h] + add;
                }
            }
        }
        __syncthreads();
    }
    for (int n = 0; n < NN; n++)
        pos[((size_t)(fb*NN + n))*H + h] = ps[n][h];
}

// ---------------- TF32 tensor-core GEMM  C = A[M,K] @ W[N,K]^T ----------------
__device__ __forceinline__ unsigned f2tf(float f)
{
    unsigned u;
    asm("cvt.rna.tf32.f32 %0, %1;" : "=r"(u) : "f"(f));
    return u;
}

#define BM  128
#define BN  128
#define BK  16
#define LDK 20       // padded k-stride (words): frag LDS conflict-free

#define EPI_BIAS   0
#define EPI_RELU   1
#define EPI_ADD    2
#define EPI_ATOMIC 3

template<int EPI>
__global__ __launch_bounds__(256)
void gemm_tc(const float* __restrict__ Ag, const float* __restrict__ Wg,
             const float* __restrict__ bias, const float* __restrict__ resid,
             float* __restrict__ Cg, int M, int N, int K)
{
    __shared__ unsigned As[2][BM][LDK];   // [buf][m][k]  20KB
    __shared__ unsigned Bs[2][BN][LDK];   // [buf][n][k]  20KB

    int m0 = blockIdx.x * BM;
    int n0 = blockIdx.y * BN;
    int per = K / gridDim.z;
    int ks  = blockIdx.z * per;
    int ke  = ks + per;

    int tid  = threadIdx.x;
    int lane = tid & 31;
    int warp = tid >> 5;
    int wm = warp >> 2;          // 0..1  (64-row slab)
    int wn = warp & 3;           // 0..3  (32-col slab)
    int gid = lane >> 2;         // 0..7
    int tg  = lane & 3;          // 0..3
    int lrow = tid >> 1;         // 0..127
    int lcol = (tid & 1) * 8;    // 0 or 8

    float acc[4][4][4];
#pragma unroll
    for (int i = 0; i < 4; i++)
#pragma unroll
        for (int j = 0; j < 4; j++)
#pragma unroll
            for (int k = 0; k < 4; k++) acc[i][j][k] = 0.f;

    const float* Ap = Ag + (size_t)(m0 + lrow) * K + lcol;
    const float* Wp = Wg + (size_t)(n0 + lrow) * K + lcol;

    float4 av0, av1, wv0, wv1;

    // prologue: load + store tile 0
    av0 = *(const float4*)(Ap + ks);
    av1 = *(const float4*)(Ap + ks + 4);
    wv0 = *(const float4*)(Wp + ks);
    wv1 = *(const float4*)(Wp + ks + 4);
    *(uint4*)&As[0][lrow][lcol]     = make_uint4(f2tf(av0.x), f2tf(av0.y), f2tf(av0.z), f2tf(av0.w));
    *(uint4*)&As[0][lrow][lcol + 4] = make_uint4(f2tf(av1.x), f2tf(av1.y), f2tf(av1.z), f2tf(av1.w));
    *(uint4*)&Bs[0][lrow][lcol]     = make_uint4(f2tf(wv0.x), f2tf(wv0.y), f2tf(wv0.z), f2tf(wv0.w));
    *(uint4*)&Bs[0][lrow][lcol + 4] = make_uint4(f2tf(wv1.x), f2tf(wv1.y), f2tf(wv1.z), f2tf(wv1.w));
    __syncthreads();

    int cur = 0;
    for (int kt = ks; kt < ke; kt += BK) {
        bool more = (kt + BK) < ke;
        if (more) {     // prefetch next tile into regs (overlaps mma below)
            av0 = *(const float4*)(Ap + kt + BK);
            av1 = *(const float4*)(Ap + kt + BK + 4);
            wv0 = *(const float4*)(Wp + kt + BK);
            wv1 = *(const float4*)(Wp + kt + BK + 4);
        }

#pragma unroll
        for (int k2 = 0; k2 < 2; k2++) {
            int kk = k2 * 8;
            unsigned af[4][4], bf[4][2];
#pragma unroll
            for (int mt = 0; mt < 4; mt++) {
                int r = wm*64 + mt*16 + gid;
                af[mt][0] = As[cur][r    ][kk + tg];
                af[mt][1] = As[cur][r + 8][kk + tg];
                af[mt][2] = As[cur][r    ][kk + tg + 4];
                af[mt][3] = As[cur][r + 8][kk + tg + 4];
            }
#pragma unroll
            for (int nt = 0; nt < 4; nt++) {
                int c = wn*32 + nt*8 + gid;
                bf[nt][0] = Bs[cur][c][kk + tg];
                bf[nt][1] = Bs[cur][c][kk + tg + 4];
            }
#pragma unroll
            for (int mt = 0; mt < 4; mt++)
#pragma unroll
                for (int nt = 0; nt < 4; nt++) {
                    asm volatile(
                        "mma.sync.aligned.m16n8k8.row.col.f32.tf32.tf32.f32 "
                        "{%0,%1,%2,%3}, {%4,%5,%6,%7}, {%8,%9}, {%0,%1,%2,%3};\n"
                        : "+f"(acc[mt][nt][0]), "+f"(acc[mt][nt][1]),
                          "+f"(acc[mt][nt][2]), "+f"(acc[mt][nt][3])
                        : "r"(af[mt][0]), "r"(af[mt][1]), "r"(af[mt][2]), "r"(af[mt][3]),
                          "r"(bf[nt][0]), "r"(bf[nt][1]));
                }
        }

        if (more) {     // store next tile into other buffer, one sync per iter
            int nxt = cur ^ 1;
            *(uint4*)&As[nxt][lrow][lcol]     = make_uint4(f2tf(av0.x), f2tf(av0.y), f2tf(av0.z), f2tf(av0.w));
            *(uint4*)&As[nxt][lrow][lcol + 4] = make_uint4(f2tf(av1.x), f2tf(av1.y), f2tf(av1.z), f2tf(av1.w));
            *(uint4*)&Bs[nxt][lrow][lcol]     = make_uint4(f2tf(wv0.x), f2tf(wv0.y), f2tf(wv0.z), f2tf(wv0.w));
            *(uint4*)&Bs[nxt][lrow][lcol + 4] = make_uint4(f2tf(wv1.x), f2tf(wv1.y), f2tf(wv1.z), f2tf(wv1.w));
            __syncthreads();
        }
        cur ^= 1;
    }

#pragma unroll
    for (int mt = 0; mt < 4; mt++) {
#pragma unroll
        for (int nt = 0; nt < 4; nt++) {
            int r = m0 + wm*64 + mt*16 + gid;
            int c = n0 + wn*32 + nt*8 + 2*tg;
            if constexpr (EPI == EPI_ATOMIC) {
                atomicAdd(&Cg[(size_t)r*N + c],         acc[mt][nt][0]);
                atomicAdd(&Cg[(size_t)r*N + c + 1],     acc[mt][nt][1]);
                atomicAdd(&Cg[(size_t)(r+8)*N + c],     acc[mt][nt][2]);
                atomicAdd(&Cg[(size_t)(r+8)*N + c + 1], acc[mt][nt][3]);
            } else {
                float b0 = bias[c], b1 = bias[c + 1];
                float v0 = acc[mt][nt][0] + b0, v1 = acc[mt][nt][1] + b1;
                float v2 = acc[mt][nt][2] + b0, v3 = acc[mt][nt][3] + b1;
                if constexpr (EPI == EPI_RELU) {
                    v0 = fmaxf(v0, 0.f); v1 = fmaxf(v1, 0.f);
                    v2 = fmaxf(v2, 0.f); v3 = fmaxf(v3, 0.f);
                }
                if constexpr (EPI == EPI_ADD) {
                    float2 rl = *(const float2*)&resid[(size_t)r*N + c];
                    float2 rh = *(const float2*)&resid[(size_t)(r+8)*N + c];
                    v0 += rl.x; v1 += rl.y; v2 += rh.x; v3 += rh.y;
                }
                *(float2*)&Cg[(size_t)r*N + c]     = make_float2(v0, v1);
                *(float2*)&Cg[(size_t)(r+8)*N + c] = make_float2(v2, v3);
            }
        }
    }
}

// ---------------- row LayerNorm over H=128 (2 rows / 256-thread block) --------
__global__ __launch_bounds__(256) void ln_k(const float* __restrict__ src,
                                            const float* __restrict__ g,
                                            const float* __restrict__ b,
                                            float* __restrict__ dst)
{
    int half = threadIdx.x >> 7;          // 0/1
    int c    = threadIdx.x & 127;
    size_t r = (size_t)blockIdx.x * 2 + half;
    float v = src[r*128 + c];
    __shared__ float red[2][4];
    int w = c >> 5, lane = c & 31;
    float s = v;
#pragma unroll
    for (int off = 16; off; off >>= 1) s += __shfl_xor_sync(0xffffffffu, s, off);
    if (lane == 0) red[half][w] = s;
    __syncthreads();
    float mu = (red[half][0] + red[half][1] + red[half][2] + red[half][3]) * (1.f/128.f);
    __syncthreads();
    float d = v - mu;
    float q = d * d;
#pragma unroll
    for (int off = 16; off; off >>= 1) q += __shfl_xor_sync(0xffffffffu, q, off);
    if (lane == 0) red[half][w] = q;
    __syncthreads();
    float var = (red[half][0] + red[half][1] + red[half][2] + red[half][3]) * (1.f/128.f);
    dst[r*128 + c] = d * rsqrtf(var + 1e-5f) * g[c] + b[c];
}

// ---------------- attention: block per forest, 8 warps ------------------------
// warp w: head = w&3, query-group = w>>2 (queries [g*21, g*21+21))
__global__ __launch_bounds__(256) void attn_k(const float* __restrict__ qkv,
                                              float* __restrict__ o)
{
    int fb = blockIdx.x;
    __shared__ float ks_[NN][H + 1];
    __shared__ float vs_[NN][H + 1];
    __shared__ float pr[8][64];

    int tid = threadIdx.x;
    for (int idx = tid; idx < NN*H; idx += 256) {
        int n = idx >> 7, c = idx & 127;
        const float* row = &qkv[((size_t)(fb*NN + n))*(3*H)];
        ks_[n][c] = row[H + c];
        vs_[n][c] = row[2*H + c];
    }
    __syncthreads();

    int warp = tid >> 5, lane = tid & 31;
    int h   = warp & 3;
    int grp = warp >> 2;
    int hc  = h * HD;
    int i0  = grp * 21;
    int i1  = i0 + 21;

    const float scale = 0.17677669529663687f;   // 1/sqrt(32)

    for (int i = i0; i < i1; i++) {
        const float4* qrow = (const float4*)&qkv[((size_t)(fb*NN + i))*(3*H) + hc];
        float q[HD];
#pragma unroll
        for (int d4 = 0; d4 < HD/4; d4++) {
            float4 t = qrow[d4];
            q[d4*4+0] = t.x; q[d4*4+1] = t.y; q[d4*4+2] = t.z; q[d4*4+3] = t.w;
        }

        float s0, s1 = -1e30f;
        {
            float acc = 0.f;
#pragma unroll
            for (int d = 0; d < HD; d++) acc += q[d] * ks_[lane][hc + d];
            s0 = acc * scale;
        }
        if (lane + 32 < NN) {
            float acc = 0.f;
#pragma unroll
            for (int d = 0; d < HD; d++) acc += q[d] * ks_[lane + 32][hc + d];
            s1 = acc * scale;
        }
        float m = fmaxf(s0, s1);
#pragma unroll
        for (int off = 16; off; off >>= 1) m = fmaxf(m, __shfl_xor_sync(0xffffffffu, m, off));
        float p0 = __expf(s0 - m);
        float p1 = (lane + 32 < NN) ? __expf(s1 - m) : 0.f;
        float sum = p0 + p1;
#pragma unroll
        for (int off = 16; off; off >>= 1) sum += __shfl_xor_sync(0xffffffffu, sum, off);
        float inv = 1.f / sum;
        pr[warp][lane]      = p0 * inv;
        pr[warp][lane + 32] = p1 * inv;
        __syncwarp();
        float acc = 0.f;
#pragma unroll
        for (int j = 0; j < NN; j++) acc += pr[warp][j] * vs_[j][hc + lane];
        o[((size_t)(fb*NN + i))*H + hc + lane] = acc;
        __syncwarp();
    }
}

// ---------------- final LN over OUT=128 ----------------
__global__ __launch_bounds__(128) void lnf_k(const float* __restrict__ fin,
                                             const float* __restrict__ bo,
                                             const float* __restrict__ g,
                                             const float* __restrict__ b,
                                             float* __restrict__ out)
{
    int r = blockIdx.x, c = threadIdx.x;
    float v = fin[(size_t)r*OUTD + c] + bo[c];
    __shared__ float red[4];
    float s = v;
#pragma unroll
    for (int off = 16; off; off >>= 1) s += __shfl_xor_sync(0xffffffffu, s, off);
    if ((c & 31) == 0) red[c >> 5] = s;
    __syncthreads();
    float mu = (red[0] + red[1] + red[2] + red[3]) * (1.f/128.f);
    __syncthreads();
    float d = v - mu;
    float q = d * d;
#pragma unroll
    for (int off = 16; off; off >>= 1) q += __shfl_xor_sync(0xffffffffu, q, off);
    if ((c & 31) == 0) red[c >> 5] = q;
    __syncthreads();
    float var = (red[0] + red[1] + red[2] + red[3]) * (1.f/128.f);
    float rs = rsqrtf(var + 1e-5f);
    out[(size_t)r*OUTD + c] = d * rs * g[c] + b[c];
}

// ---------------- launch ----------------
extern "C" void kernel_launch(void* const* d_in, const int* in_sizes, int n_in,
                              void* d_out, int out_size)
{
    const float* forest = (const float*)d_in[0];
    const int*   adj    = (const int*)  d_in[1];
    const int*   order  = (const int*)  d_in[2];
    const float* W_in   = (const float*)d_in[3];
    const float* b_in   = (const float*)d_in[4];
    const float* qkv_w  = (const float*)d_in[5];
    const float* qkv_b  = (const float*)d_in[6];
    const float* aow    = (const float*)d_in[7];
    const float* aob    = (const float*)d_in[8];
    const float* f1w    = (const float*)d_in[9];
    const float* f1b    = (const float*)d_in[10];
    const float* f2w    = (const float*)d_in[11];
    const float* f2b    = (const float*)d_in[12];
    const float* ln1g   = (const float*)d_in[13];
    const float* ln1b   = (const float*)d_in[14];
    const float* ln2g   = (const float*)d_in[15];
    const float* ln2b   = (const float*)d_in[16];
    const float* Wout   = (const float*)d_in[17];
    const float* bout   = (const float*)d_in[18];
    const float* lnfg   = (const float*)d_in[19];
    const float* lnfb   = (const float*)d_in[20];

    float *px, *ppos, *pqkv, *pfin;
    cudaGetSymbolAddress((void**)&px,   g_x);
    cudaGetSymbolAddress((void**)&ppos, g_pos);
    cudaGetSymbolAddress((void**)&pqkv, g_qkv);
    cudaGetSymbolAddress((void**)&pfin, g_fin);

    // 1) positional encoding
    pos_kernel<<<FB, 128>>>(adj, order, ppos);

    // 2) embed: x = forest @ W_in^T + b_in + pos
    gemm_tc<EPI_ADD><<<dim3(TT/BM, 1, 1), 256>>>(
        forest, W_in, b_in, ppos, px, TT, H, NIN);

    for (int l = 0; l < LL; l++) {
        // qkv = x @ qkv_w^T + b    (N = 384)
        gemm_tc<EPI_BIAS><<<dim3(TT/BM, 3, 1), 256>>>(
            px, qkv_w + (size_t)l*3*H*H, qkv_b + (size_t)l*3*H,
            nullptr, pqkv, TT, 3*H, H);
        // attention -> ppos
        attn_k<<<FB, 256>>>(pqkv, ppos);
        // t = attn_out @ aow^T + aob + x  -> pqkv ; then LN -> x
        gemm_tc<EPI_ADD><<<dim3(TT/BM, 1, 1), 256>>>(
            ppos, aow + (size_t)l*H*H, aob + (size_t)l*H, px, pqkv, TT, H, H);
        ln_k<<<TT/2, 256>>>(pqkv, ln1g + (size_t)l*H, ln1b + (size_t)l*H, px);
        // ff hidden = relu(x @ f1w^T + f1b)  -> pqkv (N = 256)
        gemm_tc<EPI_RELU><<<dim3(TT/BM, 2, 1), 256>>>(
            px, f1w + (size_t)l*FF*H, f1b + (size_t)l*FF, nullptr, pqkv, TT, FF, H);
        // t = hidden @ f2w^T + f2b + x -> ppos ; then LN -> x
        gemm_tc<EPI_ADD><<<dim3(TT/BM, 1, 1), 256>>>(
            pqkv, f2w + (size_t)l*H*FF, f2b + (size_t)l*H, px, ppos, TT, H, FF);
        ln_k<<<TT/2, 256>>>(ppos, ln2g + (size_t)l*H, ln2b + (size_t)l*H, px);
    }

    // 3) final: out = LN( x.reshape(FB, NN*H) @ Wout^T + b_out )
    cudaMemsetAsync(pfin, 0, (size_t)FB*OUTD*sizeof(float));
    gemm_tc<EPI_ATOMIC><<<dim3(FB/BM, 1, 8), 256>>>(
        px, Wout, nullptr, nullptr, pfin, FB, OUTD, NN*H);
    lnf_k<<<FB, 128>>>(pfin, bout, lnfg, lnfb, (float*)d_out);
}